// round 13
// baseline (speedup 1.0000x reference)
#include <cuda_runtime.h>
#include <cstdint>

// Problem constants
#define BATCH 128
#define TT    512
#define NBLK  256      // persistent grid: 2 batch-halves x 128 j-blocks, 2 CTAs/SM
#define NTHR  128      // 4 warps, warp tile 16x32 on CTA tile 64x32
#define SP    72       // smem row pitch in words (72 % 32 == 8 -> conflict-free LDS.64)
#define AWORDS (64 * SP)            // A region words per stage
#define SWORDS (96 * SP)            // stage words (A 64 rows + B 32 rows)
#define STAGE_B (SWORDS * 4)        // 27648 bytes
#define NSTAGE 3

// ---------------- device scratch (static, allocation-free) ----------------
__device__ __align__(16) float g_z[BATCH * 1024];         // fc output (tf32, k-permuted)
__device__ __align__(16) float g_h1[2][BATCH * 1024];     // layer-0 hidden
__device__ __align__(16) float g_h2[2][BATCH * 1024];     // layer-1 hidden
__device__ __align__(16) float g_wpack[4u * 128u * 16u * 32u * 64u]; // packed tf32, 64MB
__device__ unsigned g_bar_count;
__device__ volatile unsigned g_bar_gen;

// permutation of low-3 bits: pairs (k, k+4) adjacent -> LDS.64 fragment pairs
__device__ __host__ __forceinline__ int perm8(int i) { return ((i & 3) << 1) | ((i >> 2) & 1); }

// ---------------- helpers ----------------
__device__ __forceinline__ unsigned f2tf32(float x) {
    unsigned r;
    asm("cvt.rna.tf32.f32 %0, %1;" : "=r"(r) : "f"(x));
    return r;
}
__device__ __forceinline__ float rtf(float x) { return __uint_as_float(f2tf32(x)); }

__device__ __forceinline__ void mma_tf32(float c[4], unsigned a0, unsigned a1,
                                         unsigned a2, unsigned a3,
                                         unsigned b0, unsigned b1) {
    asm volatile(
        "mma.sync.aligned.m16n8k8.row.col.f32.tf32.tf32.f32 "
        "{%0,%1,%2,%3}, {%4,%5,%6,%7}, {%8,%9}, {%0,%1,%2,%3};"
        : "+f"(c[0]), "+f"(c[1]), "+f"(c[2]), "+f"(c[3])
        : "r"(a0), "r"(a1), "r"(a2), "r"(a3), "r"(b0), "r"(b1));
}

__device__ __forceinline__ void cp16(unsigned dst, const void* src) {
    asm volatile("cp.async.cg.shared.global [%0], [%1], 16;\n" :: "r"(dst), "l"(src));
}
#define CP_COMMIT() asm volatile("cp.async.commit_group;\n" ::: "memory")
#define CP_WAIT1()  asm volatile("cp.async.wait_group 1;\n" ::: "memory")

__device__ __forceinline__ float sigf(float x) { return 1.0f / (1.0f + __expf(-x)); }
__device__ __forceinline__ float tanh_fast(float x) {
    float e = __expf(2.0f * x);
    return 1.0f - 2.0f / (e + 1.0f);
}

// ---------------- software grid barrier (all NBLK CTAs co-resident) ----------------
__device__ __forceinline__ void grid_barrier() {
    __threadfence();
    __syncthreads();
    if (threadIdx.x == 0) {
        unsigned gen = g_bar_gen;
        if (atomicAdd(&g_bar_count, 1u) == NBLK - 1) {
            *(volatile unsigned*)&g_bar_count = 0;
            __threadfence();
            g_bar_gen = gen + 1;
        } else {
            while (g_bar_gen == gen) {}
        }
        __threadfence();
    }
    __syncthreads();
}

// ---------------- init ----------------
__global__ void init_zero_kernel() {
    int idx = blockIdx.x * 256 + threadIdx.x;
    if (idx < BATCH * 1024 * 2) {
        (&g_h1[0][0])[idx] = 0.0f;
        (&g_h2[0][0])[idx] = 0.0f;
    }
    if (idx == 0) { g_bar_count = 0; g_bar_gen = 0; }
}

// ---------------- weight pre-pack: tf32, 32-col tiles, k-permuted ----------------
// wpack[mat][nb128][kc16][rr32][kk64]; rr: gate = rr>>3, jloc = rr&7
__global__ void pack_kernel(const float* __restrict__ W0, const float* __restrict__ W1,
                            const float* __restrict__ W2, const float* __restrict__ W3) {
    int idx = blockIdx.x * 256 + threadIdx.x;   // 65536 blocks -> 16777216
    int kk  = idx & 63;
    int rr  = (idx >> 6) & 31;
    int kc  = (idx >> 11) & 15;
    int nb  = (idx >> 15) & 127;
    int mat = idx >> 22;
    const float* W = (mat == 0) ? W0 : (mat == 1) ? W1 : (mat == 2) ? W2 : W3;
    int gate = rr >> 3, jloc = rr & 7;
    int srow = gate * 1024 + nb * 8 + jloc;
    float v = W[srow * 1024 + kc * 64 + kk];
    int kkp = (kk & ~7) | perm8(kk & 7);
    g_wpack[(((size_t)(mat * 128 + nb) * 16 + kc) << 11) + rr * 64 + kkp] = rtf(v);
}

// ---------------- fc: z = x @ fc_w^T + fc_b (tf32, k-permuted store) ----------------
__global__ void fc_kernel(const float* __restrict__ x, const float* __restrict__ fcw,
                          const float* __restrict__ fcb) {
    int idx = blockIdx.x * 256 + threadIdx.x;   // b*1024 + i
    int b = idx >> 10, i = idx & 1023;
    const float4* xr = reinterpret_cast<const float4*>(x + b * 256);
    const float4* wr = reinterpret_cast<const float4*>(fcw + i * 256);
    float s = fcb[i];
    #pragma unroll 8
    for (int o = 0; o < 64; o++) {
        float4 xv = __ldg(xr + o), wv = __ldg(wr + o);
        s += xv.x * wv.x + xv.y * wv.y + xv.z * wv.z + xv.w * wv.w;
    }
    int ip = (i & ~7) | perm8(i & 7);
    g_z[b * 1024 + ip] = rtf(s);
}

// ---------------- tile compute: warp tile 16x32 of CTA 64x32, k=64 ----------------
__device__ __forceinline__ void tile_compute(const unsigned* __restrict__ st,
                                             float acc[4][4], int wm,
                                             int grp, int tig) {
    const unsigned* pa = st + (wm * 16 + grp) * SP + 2 * tig;
    const unsigned* pb = st + AWORDS + grp * SP + 2 * tig;

    uint2 a0 = *(const uint2*)pa;
    uint2 a1 = *(const uint2*)(pa + 8 * SP);
    uint2 b0 = *(const uint2*)pb;
    uint2 b1 = *(const uint2*)(pb + 8 * SP);
    uint2 b2 = *(const uint2*)(pb + 16 * SP);
    uint2 b3 = *(const uint2*)(pb + 24 * SP);

    #pragma unroll
    for (int k8 = 0; k8 < 8; k8++) {
        uint2 na0, na1, nb0, nb1, nb2, nb3;
        if (k8 < 7) {
            const unsigned* qa = pa + (k8 + 1) * 8;
            const unsigned* qb = pb + (k8 + 1) * 8;
            na0 = *(const uint2*)qa;
            na1 = *(const uint2*)(qa + 8 * SP);
            nb0 = *(const uint2*)qb;
            nb1 = *(const uint2*)(qb + 8 * SP);
            nb2 = *(const uint2*)(qb + 16 * SP);
            nb3 = *(const uint2*)(qb + 24 * SP);
        }
        mma_tf32(acc[0], a0.x, a1.x, a0.y, a1.y, b0.x, b0.y);
        mma_tf32(acc[1], a0.x, a1.x, a0.y, a1.y, b1.x, b1.y);
        mma_tf32(acc[2], a0.x, a1.x, a0.y, a1.y, b2.x, b2.y);
        mma_tf32(acc[3], a0.x, a1.x, a0.y, a1.y, b3.x, b3.y);
        if (k8 < 7) {
            a0 = na0; a1 = na1; b0 = nb0; b1 = nb1; b2 = nb2; b3 = nb3;
        }
    }
}

// ---------------- GEMM phase: acc[64x32] += A[64 x 64*nIter] @ Bpacked^T ----------------
// A slab: A0 for chunks s<16, A1 for s>=16 (layer-1 concat). B likewise.
__device__ __forceinline__ void gemm_phase(
    float acc[4][4],
    const float* __restrict__ A0, const float* __restrict__ A1,
    const float* __restrict__ B0, const float* __restrict__ B1,
    int nIter, int mb, const unsigned* shp, unsigned sb,
    int tid, int wm, int grp, int tig)
{
    #pragma unroll
    for (int j = 0; j < 4; j++)
        #pragma unroll
        for (int r = 0; r < 4; r++) acc[j][r] = 0.0f;

    const int lrow = tid >> 4;            // 0..7 base row, +8 per round
    const int c4   = (tid & 15) << 2;     // 0..60

    #define ISSUE(s) do {                                                           \
        const float* A_  = ((s) < 16) ? A0 : A1;                                    \
        const float* Bt_ = (((s) < 16) ? B0 : B1) + (((s) & 15) << 11);             \
        int kk_ = ((s) * 64) & 1023;                                                \
        unsigned so_ = sb + (unsigned)((s) % 3) * STAGE_B;                          \
        _Pragma("unroll")                                                           \
        for (int v = 0; v < 8; v++) {                                               \
            int row = lrow + v * 8;                                                 \
            cp16(so_ + (row * SP + c4) * 4,                                         \
                 A_ + (mb * 64 + row) * 1024 + kk_ + c4);                           \
        }                                                                           \
        _Pragma("unroll")                                                           \
        for (int v = 0; v < 4; v++) {                                               \
            int row = lrow + v * 8;                                                 \
            cp16(so_ + (AWORDS + row * SP + c4) * 4, Bt_ + row * 64 + c4);          \
        }                                                                           \
    } while (0)

    ISSUE(0); CP_COMMIT();
    ISSUE(1); CP_COMMIT();

    for (int it = 0; it < nIter; it++) {
        CP_WAIT1();
        __syncthreads();
        tile_compute(shp + (it % 3) * SWORDS, acc, wm, grp, tig);
        if (it + 2 < nIter) ISSUE(it + 2);
        CP_COMMIT();
    }
    #undef ISSUE
}

// ---------------- persistent LSTM kernel ----------------
__global__ void __launch_bounds__(NTHR, 2)
lstm_persistent(const float* __restrict__ bih0, const float* __restrict__ bhh0,
                const float* __restrict__ bih1, const float* __restrict__ bhh1,
                float* __restrict__ out)
{
    extern __shared__ unsigned sh[];
    const unsigned sb = (unsigned)__cvta_generic_to_shared(sh);

    const int tid  = threadIdx.x;
    const int warp = tid >> 5, lane = tid & 31;
    const int grp  = lane >> 2, tig = lane & 3;
    const int wm   = warp;                // 4 warps stacked in M
    const int mb = blockIdx.x & 1;        // batch half (2 x 64 rows)
    const int nb = blockIdx.x >> 1;       // 8-column block of j (0..127)

    const float* PB0 = g_wpack + (size_t)(0 * 128 + nb) * 32768;  // Wih0
    const float* PB1 = g_wpack + (size_t)(1 * 128 + nb) * 32768;  // Whh0
    const float* PB2 = g_wpack + (size_t)(2 * 128 + nb) * 32768;  // Wih1
    const float* PB3 = g_wpack + (size_t)(3 * 128 + nb) * 32768;  // Whh1

    float acc[4][4];
    float gx[4][4];        // layer-0 input gates + biases (time-constant)
    float b1r[4][2];       // layer-1 bias sums
    float c1r[4], c2r[4];
    #pragma unroll
    for (int i = 0; i < 4; i++) { c1r[i] = 0.0f; c2r[i] = 0.0f; }

    // prologue: gx = z @ Wih0^T + bih0 + bhh0
    gemm_phase(acc, g_z, g_z, PB0, PB0, 16, mb, sh, sb, tid, wm, grp, tig);
    #pragma unroll
    for (int g = 0; g < 4; g++)
        #pragma unroll
        for (int r = 0; r < 4; r++) {
            int n = g * 1024 + nb * 8 + 2 * tig + (r & 1);
            gx[g][r] = acc[g][r] + __ldg(bih0 + n) + __ldg(bhh0 + n);
        }
    #pragma unroll
    for (int g = 0; g < 4; g++)
        #pragma unroll
        for (int c = 0; c < 2; c++) {
            int n = g * 1024 + nb * 8 + 2 * tig + c;
            b1r[g][c] = __ldg(bih1 + n) + __ldg(bhh1 + n);
        }

    const int rowb = mb * 64 + wm * 16 + grp;   // base batch row
    const int jb   = nb * 8;                    // logical 8-col group base

    for (int t = 0; t < TT; t++) {
        const int q = t & 1, p = q ^ 1;

        // layer 0: h1_prev @ Whh0^T (+gx) -> h1[q], c1
        gemm_phase(acc, g_h1[p], g_h1[p], PB1, PB1, 16, mb, sh, sb,
                   tid, wm, grp, tig);
        #pragma unroll
        for (int r = 0; r < 4; r++) {
            float si = acc[0][r] + gx[0][r];
            float sf = acc[1][r] + gx[1][r];
            float sg = acc[2][r] + gx[2][r];
            float so = acc[3][r] + gx[3][r];
            float cv = sigf(sf) * c1r[r] + sigf(si) * tanh_fast(sg);
            c1r[r] = cv;
            float h = sigf(so) * tanh_fast(cv);
            int row = rowb + ((r & 2) ? 8 : 0);
            int i3 = 2 * tig + (r & 1);
            __stcg(&g_h1[q][row * 1024 + jb + perm8(i3)], rtf(h));
        }

        grid_barrier();   // single per-timestep sync; slot parity covers other hazards

        // layer 1: [h1[q] | h2[p]] @ [Wih1 | Whh1]^T -> h2[q], c2, out
        gemm_phase(acc, g_h1[q], g_h2[p], PB2, PB3, 32, mb, sh, sb,
                   tid, wm, grp, tig);
        #pragma unroll
        for (int rh = 0; rh < 2; rh++) {
            float hv[2];
            #pragma unroll
            for (int c = 0; c < 2; c++) {
                int r = rh * 2 + c;
                float si = acc[0][r] + b1r[0][c];
                float sf = acc[1][r] + b1r[1][c];
                float sg = acc[2][r] + b1r[2][c];
                float so = acc[3][r] + b1r[3][c];
                float cv = sigf(sf) * c2r[r] + sigf(si) * tanh_fast(sg);
                c2r[r] = cv;
                float h = sigf(so) * tanh_fast(cv);
                hv[c] = h;
                int row = rowb + rh * 8;
                int i3 = 2 * tig + c;
                __stcg(&g_h2[q][row * 1024 + jb + perm8(i3)], rtf(h));
            }
            int row = rowb + rh * 8;
            *reinterpret_cast<float2*>(out + ((size_t)row * TT + t) * 1024 + jb + 2 * tig) =
                make_float2(hv[0], hv[1]);   // full-precision output
        }
    }
}

// ---------------- launch ----------------
extern "C" void kernel_launch(void* const* d_in, const int* in_sizes, int n_in,
                              void* d_out, int out_size) {
    const float* x    = (const float*)d_in[0];
    const float* fc_w = (const float*)d_in[1];
    const float* fc_b = (const float*)d_in[2];
    const float* Wih0 = (const float*)d_in[3];
    const float* Whh0 = (const float*)d_in[4];
    const float* bih0 = (const float*)d_in[5];
    const float* bhh0 = (const float*)d_in[6];
    const float* Wih1 = (const float*)d_in[7];
    const float* Whh1 = (const float*)d_in[8];
    const float* bih1 = (const float*)d_in[9];
    const float* bhh1 = (const float*)d_in[10];
    float* out = (float*)d_out;

    static int smem_set = 0;
    const int smem_bytes = NSTAGE * STAGE_B;   // 82944 -> 2 CTAs/SM
    if (!smem_set) {
        cudaFuncSetAttribute(lstm_persistent,
                             cudaFuncAttributeMaxDynamicSharedMemorySize, smem_bytes);
        smem_set = 1;
    }

    init_zero_kernel<<<1024, 256>>>();
    pack_kernel<<<65536, 256>>>(Wih0, Whh0, Wih1, Whh1);
    fc_kernel<<<512, 256>>>(x, fc_w, fc_b);
    lstm_persistent<<<NBLK, NTHR, smem_bytes>>>(bih0, bhh0, bih1, bhh1, out);
}

// round 14
// speedup vs baseline: 1.7736x; 1.7736x over previous
#include <cuda_runtime.h>
#include <cuda_fp16.h>
#include <cstdint>

// Problem constants
#define BATCH 128
#define TT    512
#define NBLK  128      // persistent grid (all co-resident, 1 CTA/SM balanced)
#define NTHR  256      // 8 warps: wm=warp>>1 (16 rows), wn=warp&1 (32 cols)
#define SP    40       // smem row pitch in WORDS (40 % 32 == 8 -> conflict-free LDS.64)
#define TILEW (64 * SP)        // words per 64x(64 halves) tile buffer (2560)
#define NSTAGE 4

// ---------------- device scratch (static, allocation-free) ----------------
__device__ __align__(16) __half g_z[BATCH * 1024];         // fc output (fp16, pair-permuted)
__device__ __align__(16) __half g_h1[2][BATCH * 1024];     // layer-0 hidden
__device__ __align__(16) __half g_h2[2][BATCH * 1024];     // layer-1 hidden
__device__ __align__(16) __half g_wpack[4u * 64u * 16u * 4096u]; // packed fp16 weights, 32MB
__device__ unsigned g_bar_count;
__device__ volatile unsigned g_bar_gen;

// pair permutation: within each 16-half group, pair p (halves 2p,2p+1) goes to
// stored pair slot perm8(p) so logical pairs (t, t+4) are adjacent -> one LDS.64
__device__ __host__ __forceinline__ int perm8(int i) { return ((i & 3) << 1) | ((i >> 2) & 1); }
__device__ __forceinline__ int permh(int k) {        // full stored index of logical half k
    return (k & ~15) | (perm8((k >> 1) & 7) * 2 + (k & 1));
}

// ---------------- helpers ----------------
__device__ __forceinline__ void mma_f16(float c[4], unsigned a0, unsigned a1,
                                        unsigned a2, unsigned a3,
                                        unsigned b0, unsigned b1) {
    asm volatile(
        "mma.sync.aligned.m16n8k16.row.col.f32.f16.f16.f32 "
        "{%0,%1,%2,%3}, {%4,%5,%6,%7}, {%8,%9}, {%0,%1,%2,%3};"
        : "+f"(c[0]), "+f"(c[1]), "+f"(c[2]), "+f"(c[3])
        : "r"(a0), "r"(a1), "r"(a2), "r"(a3), "r"(b0), "r"(b1));
}

__device__ __forceinline__ void cp16(unsigned dst, const void* src) {
    asm volatile("cp.async.cg.shared.global [%0], [%1], 16;\n" :: "r"(dst), "l"(src));
}
#define CP_COMMIT() asm volatile("cp.async.commit_group;\n" ::: "memory")
#define CP_WAIT2()  asm volatile("cp.async.wait_group 2;\n" ::: "memory")

__device__ __forceinline__ float sigf(float x) { return 1.0f / (1.0f + __expf(-x)); }
__device__ __forceinline__ float tanh_fast(float x) {
    float e = __expf(2.0f * x);
    return 1.0f - 2.0f / (e + 1.0f);
}

// ---------------- software grid barrier ----------------
__device__ __forceinline__ void grid_barrier() {
    __threadfence();
    __syncthreads();
    if (threadIdx.x == 0) {
        unsigned gen = g_bar_gen;
        if (atomicAdd(&g_bar_count, 1u) == NBLK - 1) {
            *(volatile unsigned*)&g_bar_count = 0;
            __threadfence();
            g_bar_gen = gen + 1;
        } else {
            while (g_bar_gen == gen) {}
        }
        __threadfence();
    }
    __syncthreads();
}

// ---------------- init ----------------
__global__ void init_zero_kernel() {
    int idx = blockIdx.x * 256 + threadIdx.x;   // 1024 blocks -> 262144 uints
    if (idx < BATCH * 1024) {                   // 131072 uints = 262144 halves per pair
        reinterpret_cast<unsigned*>(&g_h1[0][0])[idx] = 0u;
        reinterpret_cast<unsigned*>(&g_h2[0][0])[idx] = 0u;
    }
    if (idx == 0) { g_bar_count = 0; g_bar_gen = 0; }
}

// ---------------- weight pre-pack: fp16, tile-native, pair-permuted ----------------
// wpack[mat][nb][kc16][rr64][kk64]; rr: gate=(rr>>3)&3, jloc=(rr&7)+((rr>>5)<<3)
__global__ void pack_kernel(const float* __restrict__ W0, const float* __restrict__ W1,
                            const float* __restrict__ W2, const float* __restrict__ W3) {
    int idx = blockIdx.x * 256 + threadIdx.x;   // 65536 blocks -> 16777216
    int kk  = idx & 63;
    int rr  = (idx >> 6) & 63;
    int kc  = (idx >> 12) & 15;
    int nb  = (idx >> 16) & 63;
    int mat = idx >> 22;
    const float* W = (mat == 0) ? W0 : (mat == 1) ? W1 : (mat == 2) ? W2 : W3;
    int gate = (rr >> 3) & 3;
    int jloc = (rr & 7) + ((rr >> 5) << 3);
    int srow = gate * 1024 + nb * 16 + jloc;
    float v = W[srow * 1024 + kc * 64 + kk];
    g_wpack[(((size_t)(mat * 64 + nb) * 16 + kc) << 12) + rr * 64 + permh(kk)] =
        __float2half_rn(v);
}

// ---------------- fc: z = x @ fc_w^T + fc_b (fp16, pair-permuted store) ----------------
__global__ void fc_kernel(const float* __restrict__ x, const float* __restrict__ fcw,
                          const float* __restrict__ fcb) {
    int idx = blockIdx.x * 256 + threadIdx.x;   // b*1024 + i
    int b = idx >> 10, i = idx & 1023;
    const float4* xr = reinterpret_cast<const float4*>(x + b * 256);
    const float4* wr = reinterpret_cast<const float4*>(fcw + i * 256);
    float s = fcb[i];
    #pragma unroll 8
    for (int o = 0; o < 64; o++) {
        float4 xv = __ldg(xr + o), wv = __ldg(wr + o);
        s += xv.x * wv.x + xv.y * wv.y + xv.z * wv.z + xv.w * wv.w;
    }
    g_z[b * 1024 + permh(i)] = __float2half_rn(s);
}

// ---------------- tile compute: warp 16x32 of CTA 64x64, k=64 (4 k16 groups) ----------
__device__ __forceinline__ void tile_compute(const unsigned* __restrict__ as,
                                             const unsigned* __restrict__ bs,
                                             float acc[4][4], int wm, int wn,
                                             int grp, int tig) {
    const unsigned* pa = as + (wm * 16 + grp) * SP + 2 * tig;
    const unsigned* pb = bs + (wn * 32 + grp) * SP + 2 * tig;

    uint2 a0 = *(const uint2*)pa;               // row grp:   (a0, a2)
    uint2 a1 = *(const uint2*)(pa + 8 * SP);    // row grp+8: (a1, a3)
    uint2 b0 = *(const uint2*)pb;
    uint2 b1 = *(const uint2*)(pb + 8 * SP);
    uint2 b2 = *(const uint2*)(pb + 16 * SP);
    uint2 b3 = *(const uint2*)(pb + 24 * SP);

    #pragma unroll
    for (int g = 0; g < 4; g++) {
        uint2 na0, na1, nb0, nb1, nb2, nb3;
        if (g < 3) {
            const unsigned* qa = pa + (g + 1) * 8;
            const unsigned* qb = pb + (g + 1) * 8;
            na0 = *(const uint2*)qa;
            na1 = *(const uint2*)(qa + 8 * SP);
            nb0 = *(const uint2*)qb;
            nb1 = *(const uint2*)(qb + 8 * SP);
            nb2 = *(const uint2*)(qb + 16 * SP);
            nb3 = *(const uint2*)(qb + 24 * SP);
        }
        mma_f16(acc[0], a0.x, a1.x, a0.y, a1.y, b0.x, b0.y);
        mma_f16(acc[1], a0.x, a1.x, a0.y, a1.y, b1.x, b1.y);
        mma_f16(acc[2], a0.x, a1.x, a0.y, a1.y, b2.x, b2.y);
        mma_f16(acc[3], a0.x, a1.x, a0.y, a1.y, b3.x, b3.y);
        if (g < 3) {
            a0 = na0; a1 = na1; b0 = nb0; b1 = nb1; b2 = nb2; b3 = nb3;
        }
    }
}

// ---------------- GEMM phase: acc[64x64] += A[64 x 64*nIter] @ Bpacked^T ----------------
__device__ __forceinline__ void gemm_phase(
    float acc[4][4],
    const __half* __restrict__ A0, const __half* __restrict__ A1,
    const __half* __restrict__ B0, const __half* __restrict__ B1,
    int nIter, int mb, unsigned* As, unsigned* Bs,
    unsigned AsBase, unsigned BsBase,
    int tid, int wm, int wn, int grp, int tig)
{
    #pragma unroll
    for (int j = 0; j < 4; j++)
        #pragma unroll
        for (int r = 0; r < 4; r++) acc[j][r] = 0.0f;

    // 512 cp16 each for A and B per chunk; 2 A + 2 B per thread
    #define ISSUE(s) do {                                                           \
        const __half* A_  = ((s) < 16) ? A0 : A1;                                   \
        const __half* Bt_ = (((s) < 16) ? B0 : B1) + (((s) & 15) << 12);            \
        int kk_ = ((s) * 64) & 1023;                                                \
        unsigned so_ = ((s) & 3) * (TILEW * 4);                                     \
        _Pragma("unroll")                                                           \
        for (int v = 0; v < 2; v++) {                                               \
            int idx = tid + (v << 8);                                               \
            int row = idx >> 3, c = idx & 7;                                        \
            cp16(AsBase + so_ + (row * SP + c * 4) * 4,                             \
                 A_ + (mb * 64 + row) * 1024 + kk_ + c * 8);                        \
            cp16(BsBase + so_ + (row * SP + c * 4) * 4, Bt_ + row * 64 + c * 8);    \
        }                                                                           \
    } while (0)

    ISSUE(0); CP_COMMIT();
    ISSUE(1); CP_COMMIT();
    ISSUE(2); CP_COMMIT();

    for (int it = 0; it < nIter; it++) {
        CP_WAIT2();
        __syncthreads();
        tile_compute(As + (it & 3) * TILEW, Bs + (it & 3) * TILEW,
                     acc, wm, wn, grp, tig);
        if (it + 3 < nIter) ISSUE(it + 3);
        CP_COMMIT();
    }
    #undef ISSUE
}

// ---------------- persistent LSTM kernel ----------------
__global__ void __launch_bounds__(NTHR, 1)
lstm_persistent(const float* __restrict__ bih0, const float* __restrict__ bhh0,
                const float* __restrict__ bih1, const float* __restrict__ bhh1,
                float* __restrict__ out)
{
    extern __shared__ unsigned sh[];
    unsigned* As = sh;
    unsigned* Bs = sh + NSTAGE * TILEW;
    const unsigned AsBase = (unsigned)__cvta_generic_to_shared(As);
    const unsigned BsBase = (unsigned)__cvta_generic_to_shared(Bs);

    const int tid  = threadIdx.x;
    const int warp = tid >> 5, lane = tid & 31;
    const int grp  = lane >> 2, tig = lane & 3;
    const int wm   = warp >> 1, wn = warp & 1;
    const int mb = blockIdx.x & 1;        // batch block (2 x 64 rows)
    const int nb = blockIdx.x >> 1;       // 16-column block of j (0..63)

    const __half* PB0 = g_wpack + (size_t)(0 * 64 + nb) * 65536;  // Wih0
    const __half* PB1 = g_wpack + (size_t)(1 * 64 + nb) * 65536;  // Whh0
    const __half* PB2 = g_wpack + (size_t)(2 * 64 + nb) * 65536;  // Wih1
    const __half* PB3 = g_wpack + (size_t)(3 * 64 + nb) * 65536;  // Whh1

    float acc[4][4];
    float gx[4][4];        // layer-0 input gates + biases (time-constant)
    float b1r[4][2];       // layer-1 bias sums
    float c1r[4], c2r[4];
    #pragma unroll
    for (int i = 0; i < 4; i++) { c1r[i] = 0.0f; c2r[i] = 0.0f; }

    // prologue: gx = z @ Wih0^T + bih0 + bhh0
    gemm_phase(acc, g_z, g_z, PB0, PB0, 16, mb, As, Bs, AsBase, BsBase,
               tid, wm, wn, grp, tig);
    #pragma unroll
    for (int g = 0; g < 4; g++)
        #pragma unroll
        for (int r = 0; r < 4; r++) {
            int n = g * 1024 + nb * 16 + wn * 8 + 2 * tig + (r & 1);
            gx[g][r] = acc[g][r] + __ldg(bih0 + n) + __ldg(bhh0 + n);
        }
    #pragma unroll
    for (int g = 0; g < 4; g++)
        #pragma unroll
        for (int c = 0; c < 2; c++) {
            int n = g * 1024 + nb * 16 + wn * 8 + 2 * tig + c;
            b1r[g][c] = __ldg(bih1 + n) + __ldg(bhh1 + n);
        }

    const int rowb = mb * 64 + wm * 16 + grp;           // base batch row
    const int hoff = nb * 16 + 4 * tig + 2 * wn;        // stored half2 offset (pair-perm)
    const int jlog = nb * 16 + wn * 8 + 2 * tig;        // logical j base (for out)

    for (int t = 0; t < TT; t++) {
        const int q = t & 1, p = q ^ 1;

        // layer 0: h1_prev @ Whh0^T (+gx) -> h1[q], c1
        gemm_phase(acc, g_h1[p], g_h1[p], PB1, PB1, 16, mb, As, Bs, AsBase, BsBase,
                   tid, wm, wn, grp, tig);
        #pragma unroll
        for (int rh = 0; rh < 2; rh++) {
            __half hh[2];
            #pragma unroll
            for (int c = 0; c < 2; c++) {
                int r = rh * 2 + c;
                float si = acc[0][r] + gx[0][r];
                float sf = acc[1][r] + gx[1][r];
                float sg = acc[2][r] + gx[2][r];
                float so = acc[3][r] + gx[3][r];
                float cv = sigf(sf) * c1r[r] + sigf(si) * tanh_fast(sg);
                c1r[r] = cv;
                hh[c] = __float2half_rn(sigf(so) * tanh_fast(cv));
            }
            int row = rowb + rh * 8;
            __half2 hv; hv.x = hh[0]; hv.y = hh[1];
            __stcg(reinterpret_cast<__half2*>(&g_h1[q][row * 1024 + hoff]), hv);
        }

        grid_barrier();   // single per-timestep sync; slot parity covers other hazards

        // layer 1: [h1[q] | h2[p]] @ [Wih1 | Whh1]^T -> h2[q], c2, out
        gemm_phase(acc, g_h1[q], g_h2[p], PB2, PB3, 32, mb, As, Bs, AsBase, BsBase,
                   tid, wm, wn, grp, tig);
        #pragma unroll
        for (int rh = 0; rh < 2; rh++) {
            float ho[2];
            __half hh[2];
            #pragma unroll
            for (int c = 0; c < 2; c++) {
                int r = rh * 2 + c;
                float si = acc[0][r] + b1r[0][c];
                float sf = acc[1][r] + b1r[1][c];
                float sg = acc[2][r] + b1r[2][c];
                float so = acc[3][r] + b1r[3][c];
                float cv = sigf(sf) * c2r[r] + sigf(si) * tanh_fast(sg);
                c2r[r] = cv;
                float h = sigf(so) * tanh_fast(cv);
                ho[c] = h;
                hh[c] = __float2half_rn(h);
            }
            int row = rowb + rh * 8;
            __half2 hv; hv.x = hh[0]; hv.y = hh[1];
            __stcg(reinterpret_cast<__half2*>(&g_h2[q][row * 1024 + hoff]), hv);
            *reinterpret_cast<float2*>(out + ((size_t)row * TT + t) * 1024 + jlog) =
                make_float2(ho[0], ho[1]);   // full-precision output
        }
    }
}

// ---------------- launch ----------------
extern "C" void kernel_launch(void* const* d_in, const int* in_sizes, int n_in,
                              void* d_out, int out_size) {
    const float* x    = (const float*)d_in[0];
    const float* fc_w = (const float*)d_in[1];
    const float* fc_b = (const float*)d_in[2];
    const float* Wih0 = (const float*)d_in[3];
    const float* Whh0 = (const float*)d_in[4];
    const float* bih0 = (const float*)d_in[5];
    const float* bhh0 = (const float*)d_in[6];
    const float* Wih1 = (const float*)d_in[7];
    const float* Whh1 = (const float*)d_in[8];
    const float* bih1 = (const float*)d_in[9];
    const float* bhh1 = (const float*)d_in[10];
    float* out = (float*)d_out;

    static int smem_set = 0;
    const int smem_bytes = 2 * NSTAGE * TILEW * 4;   // 81920
    if (!smem_set) {
        cudaFuncSetAttribute(lstm_persistent,
                             cudaFuncAttributeMaxDynamicSharedMemorySize, smem_bytes);
        smem_set = 1;
    }

    init_zero_kernel<<<1024, 256>>>();
    pack_kernel<<<65536, 256>>>(Wih0, Whh0, Wih1, Whh1);
    fc_kernel<<<512, 256>>>(x, fc_w, fc_b);
    lstm_persistent<<<NBLK, NTHR, smem_bytes>>>(bih0, bhh0, bih1, bhh1, out);
}

// round 15
// speedup vs baseline: 1.8631x; 1.0505x over previous
#include <cuda_runtime.h>
#include <cuda_fp16.h>
#include <cstdint>

// Problem constants
#define BATCH 128
#define TT    512
#define NBLK  128      // persistent grid (all co-resident, 1 CTA/SM)
#define NTHR  256      // 8 warps: wm=warp>>1 (16 rows), wn=warp&1 (32 cols)
#define SP    40       // smem row pitch in WORDS (40 % 32 == 8 -> conflict-free LDS.64)
#define TILEW (64 * SP)        // words per 64-row half-tile buffer (2560)
#define NSTAGE 4

// ---------------- device scratch (static, allocation-free) ----------------
__device__ __align__(16) __half g_z[BATCH * 1024];         // fc output (fp16, pair-permuted)
__device__ __align__(16) __half g_h1[2][BATCH * 1024];     // layer-0 hidden
__device__ __align__(16) __half g_h2[2][BATCH * 1024];     // layer-1 hidden
__device__ __align__(16) __half g_wpack[4u * 64u * 16u * 4096u]; // packed fp16 weights, 32MB
__device__ unsigned g_bar_count;
__device__ volatile unsigned g_bar_gen;

// pair permutation: within each 16-half group, pair p -> slot perm8(p): logical
// (t, t+4) pairs adjacent -> one LDS.64 per mma operand pair
__device__ __host__ __forceinline__ int perm8(int i) { return ((i & 3) << 1) | ((i >> 2) & 1); }
__device__ __forceinline__ int permh(int k) {
    return (k & ~15) | (perm8((k >> 1) & 7) * 2 + (k & 1));
}

// ---------------- helpers ----------------
__device__ __forceinline__ void mma_f16(float c[4], unsigned a0, unsigned a1,
                                        unsigned a2, unsigned a3,
                                        unsigned b0, unsigned b1) {
    asm volatile(
        "mma.sync.aligned.m16n8k16.row.col.f32.f16.f16.f32 "
        "{%0,%1,%2,%3}, {%4,%5,%6,%7}, {%8,%9}, {%0,%1,%2,%3};"
        : "+f"(c[0]), "+f"(c[1]), "+f"(c[2]), "+f"(c[3])
        : "r"(a0), "r"(a1), "r"(a2), "r"(a3), "r"(b0), "r"(b1));
}

__device__ __forceinline__ void cp16(unsigned dst, const void* src) {
    asm volatile("cp.async.cg.shared.global [%0], [%1], 16;\n" :: "r"(dst), "l"(src));
}
#define CP_COMMIT() asm volatile("cp.async.commit_group;\n" ::: "memory")
#define CP_WAIT2()  asm volatile("cp.async.wait_group 2;\n" ::: "memory")

__device__ __forceinline__ float sigf(float x) { return 1.0f / (1.0f + __expf(-x)); }
__device__ __forceinline__ float tanh_fast(float x) {
    float e = __expf(2.0f * x);
    return 1.0f - 2.0f / (e + 1.0f);
}

// ---------------- software grid barrier ----------------
__device__ __forceinline__ void grid_barrier() {
    __threadfence();
    __syncthreads();
    if (threadIdx.x == 0) {
        unsigned gen = g_bar_gen;
        if (atomicAdd(&g_bar_count, 1u) == NBLK - 1) {
            *(volatile unsigned*)&g_bar_count = 0;
            __threadfence();
            g_bar_gen = gen + 1;
        } else {
            while (g_bar_gen == gen) {}
        }
        __threadfence();
    }
    __syncthreads();
}

// ---------------- init ----------------
__global__ void init_zero_kernel() {
    int idx = blockIdx.x * 256 + threadIdx.x;
    if (idx < BATCH * 1024) {
        reinterpret_cast<unsigned*>(&g_h1[0][0])[idx] = 0u;
        reinterpret_cast<unsigned*>(&g_h2[0][0])[idx] = 0u;
    }
    if (idx == 0) { g_bar_count = 0; g_bar_gen = 0; }
}

// ---------------- weight pre-pack: fp16, tile-native, pair-permuted ----------------
// wpack[mat][nb][kc16][rr64][kk64]; rr: gate=(rr>>3)&3, jloc=(rr&7)+((rr>>5)<<3)
__global__ void pack_kernel(const float* __restrict__ W0, const float* __restrict__ W1,
                            const float* __restrict__ W2, const float* __restrict__ W3) {
    int idx = blockIdx.x * 256 + threadIdx.x;
    int kk  = idx & 63;
    int rr  = (idx >> 6) & 63;
    int kc  = (idx >> 12) & 15;
    int nb  = (idx >> 16) & 63;
    int mat = idx >> 22;
    const float* W = (mat == 0) ? W0 : (mat == 1) ? W1 : (mat == 2) ? W2 : W3;
    int gate = (rr >> 3) & 3;
    int jloc = (rr & 7) + ((rr >> 5) << 3);
    int srow = gate * 1024 + nb * 16 + jloc;
    float v = W[srow * 1024 + kc * 64 + kk];
    g_wpack[(((size_t)(mat * 64 + nb) * 16 + kc) << 12) + rr * 64 + permh(kk)] =
        __float2half_rn(v);
}

// ---------------- fc: z = x @ fc_w^T + fc_b (fp16, pair-permuted store) ----------------
__global__ void fc_kernel(const float* __restrict__ x, const float* __restrict__ fcw,
                          const float* __restrict__ fcb) {
    int idx = blockIdx.x * 256 + threadIdx.x;
    int b = idx >> 10, i = idx & 1023;
    const float4* xr = reinterpret_cast<const float4*>(x + b * 256);
    const float4* wr = reinterpret_cast<const float4*>(fcw + i * 256);
    float s = fcb[i];
    #pragma unroll 8
    for (int o = 0; o < 64; o++) {
        float4 xv = __ldg(xr + o), wv = __ldg(wr + o);
        s += xv.x * wv.x + xv.y * wv.y + xv.z * wv.z + xv.w * wv.w;
    }
    g_z[b * 1024 + permh(i)] = __float2half_rn(s);
}

// ---------------- issue helpers (one ring slot each) ----------------
// Arow: A base already offset by mb*64*1024 + koff; Bt: packed B chunk base.
__device__ __forceinline__ void issue_AB(const __half* __restrict__ Arow,
                                         const __half* __restrict__ Bt,
                                         unsigned AsBase, unsigned BsBase,
                                         int slot, int tid) {
    unsigned so = (unsigned)slot * (TILEW * 4);
    #pragma unroll
    for (int v = 0; v < 2; v++) {
        int idx = tid + (v << 8);
        int row = idx >> 3, c = idx & 7;
        cp16(AsBase + so + (row * SP + c * 4) * 4, Arow + row * 1024 + c * 8);
        cp16(BsBase + so + (row * SP + c * 4) * 4, Bt + row * 64 + c * 8);
    }
}
__device__ __forceinline__ void issue_A(const __half* __restrict__ Arow,
                                        unsigned AsBase, int slot, int tid) {
    unsigned so = (unsigned)slot * (TILEW * 4);
    #pragma unroll
    for (int v = 0; v < 2; v++) {
        int idx = tid + (v << 8);
        int row = idx >> 3, c = idx & 7;
        cp16(AsBase + so + (row * SP + c * 4) * 4, Arow + row * 1024 + c * 8);
    }
}
__device__ __forceinline__ void issue_B(const __half* __restrict__ Bt,
                                        unsigned BsBase, int slot, int tid) {
    unsigned so = (unsigned)slot * (TILEW * 4);
    #pragma unroll
    for (int v = 0; v < 2; v++) {
        int idx = tid + (v << 8);
        int row = idx >> 3, c = idx & 7;
        cp16(BsBase + so + (row * SP + c * 4) * 4, Bt + row * 64 + c * 8);
    }
}

// ---------------- tile compute: warp 16x32 of CTA 64x64, k=64 (4 k16 groups) ----------
__device__ __forceinline__ void tile_compute(const unsigned* __restrict__ as,
                                             const unsigned* __restrict__ bs,
                                             float acc[4][4], int wm, int wn,
                                             int grp, int tig) {
    const unsigned* pa = as + (wm * 16 + grp) * SP + 2 * tig;
    const unsigned* pb = bs + (wn * 32 + grp) * SP + 2 * tig;

    uint2 a0 = *(const uint2*)pa;
    uint2 a1 = *(const uint2*)(pa + 8 * SP);
    uint2 b0 = *(const uint2*)pb;
    uint2 b1 = *(const uint2*)(pb + 8 * SP);
    uint2 b2 = *(const uint2*)(pb + 16 * SP);
    uint2 b3 = *(const uint2*)(pb + 24 * SP);

    #pragma unroll
    for (int g = 0; g < 4; g++) {
        uint2 na0, na1, nb0, nb1, nb2, nb3;
        if (g < 3) {
            const unsigned* qa = pa + (g + 1) * 8;
            const unsigned* qb = pb + (g + 1) * 8;
            na0 = *(const uint2*)qa;
            na1 = *(const uint2*)(qa + 8 * SP);
            nb0 = *(const uint2*)qb;
            nb1 = *(const uint2*)(qb + 8 * SP);
            nb2 = *(const uint2*)(qb + 16 * SP);
            nb3 = *(const uint2*)(qb + 24 * SP);
        }
        mma_f16(acc[0], a0.x, a1.x, a0.y, a1.y, b0.x, b0.y);
        mma_f16(acc[1], a0.x, a1.x, a0.y, a1.y, b1.x, b1.y);
        mma_f16(acc[2], a0.x, a1.x, a0.y, a1.y, b2.x, b2.y);
        mma_f16(acc[3], a0.x, a1.x, a0.y, a1.y, b3.x, b3.y);
        if (g < 3) {
            a0 = na0; a1 = na1; b0 = nb0; b1 = nb1; b2 = nb2; b3 = nb3;
        }
    }
}

// ---------------- persistent LSTM kernel ----------------
__global__ void __launch_bounds__(NTHR, 1)
lstm_persistent(const float* __restrict__ bih0, const float* __restrict__ bhh0,
                const float* __restrict__ bih1, const float* __restrict__ bhh1,
                float* __restrict__ out)
{
    extern __shared__ unsigned sh[];
    unsigned* As = sh;
    unsigned* Bs = sh + NSTAGE * TILEW;
    const unsigned AsBase = (unsigned)__cvta_generic_to_shared(As);
    const unsigned BsBase = (unsigned)__cvta_generic_to_shared(Bs);

    const int tid  = threadIdx.x;
    const int warp = tid >> 5, lane = tid & 31;
    const int grp  = lane >> 2, tig = lane & 3;
    const int wm   = warp >> 1, wn = warp & 1;
    const int mb = blockIdx.x & 1;        // batch block (2 x 64 rows)
    const int nb = blockIdx.x >> 1;       // 16-column block of j (0..63)
    const int mboff = mb * 64 * 1024;

    const __half* PB0 = g_wpack + (size_t)(0 * 64 + nb) * 65536;  // Wih0
    const __half* PB1 = g_wpack + (size_t)(1 * 64 + nb) * 65536;  // Whh0
    const __half* PB2 = g_wpack + (size_t)(2 * 64 + nb) * 65536;  // Wih1
    const __half* PB3 = g_wpack + (size_t)(3 * 64 + nb) * 65536;  // Whh1

    float acc[4][4];
    float gx[4][4];        // layer-0 input gates + biases (time-constant)
    float b1r[4][2];       // layer-1 bias sums
    float c1r[4], c2r[4];
    #pragma unroll
    for (int i = 0; i < 4; i++) { c1r[i] = 0.0f; c2r[i] = 0.0f; }

    #define ZACC() do { _Pragma("unroll") for (int j_ = 0; j_ < 4; j_++) \
        _Pragma("unroll") for (int r_ = 0; r_ < 4; r_++) acc[j_][r_] = 0.0f; } while (0)
    #define COMPUTE(s) tile_compute(As + ((s) & 3) * TILEW, Bs + ((s) & 3) * TILEW, \
                                    acc, wm, wn, grp, tig)

    // ---- prologue fill: gx chunks 0..2 ----
    const __half* Az = g_z + mboff;
    issue_AB(Az,       PB0,        AsBase, BsBase, 0, tid); CP_COMMIT();
    issue_AB(Az + 64,  PB0 + 4096, AsBase, BsBase, 1, tid); CP_COMMIT();
    issue_AB(Az + 128, PB0 + 8192, AsBase, BsBase, 2, tid); CP_COMMIT();

    // ---- gx GEMM: z @ Wih0^T; tail issues L0(t=0) chunks 0..2 ----
    ZACC();
    {
        const __half* H1p0 = g_h1[1] + mboff;   // p(t=0) = 1 (zeros)
        #pragma unroll 4
        for (int it = 0; it < 16; it++) {
            CP_WAIT2();
            __syncthreads();
            COMPUTE(it);
            if (it < 13) issue_AB(Az + (it + 3) * 64, PB0 + (it + 3) * 4096,
                                  AsBase, BsBase, (it + 3) & 3, tid);
            else         issue_AB(H1p0 + (it - 13) * 64, PB1 + (it - 13) * 4096,
                                  AsBase, BsBase, (it - 13) & 3, tid);
            CP_COMMIT();
        }
    }
    #pragma unroll
    for (int g = 0; g < 4; g++)
        #pragma unroll
        for (int r = 0; r < 4; r++) {
            int n = g * 1024 + nb * 16 + wn * 8 + 2 * tig + (r & 1);
            gx[g][r] = acc[g][r] + __ldg(bih0 + n) + __ldg(bhh0 + n);
        }
    #pragma unroll
    for (int g = 0; g < 4; g++)
        #pragma unroll
        for (int c = 0; c < 2; c++) {
            int n = g * 1024 + nb * 16 + wn * 8 + 2 * tig + c;
            b1r[g][c] = __ldg(bih1 + n) + __ldg(bhh1 + n);
        }

    const int rowb = mb * 64 + wm * 16 + grp;           // base batch row
    const int hoff = nb * 16 + 4 * tig + 2 * wn;        // stored half2 offset (pair-perm)
    const int jlog = nb * 16 + wn * 8 + 2 * tig;        // logical j base (for out)

    for (int t = 0; t < TT; t++) {
        const int q = t & 1, p = q ^ 1;
        const __half* H1p = g_h1[p] + mboff;
        const __half* H1q = g_h1[q] + mboff;
        const __half* H2p = g_h2[p] + mboff;

        // ---- layer 0 GEMM (chunks 0..2 already in flight); tail: L1 B-only 0..2 ----
        ZACC();
        #pragma unroll 4
        for (int it = 0; it < 16; it++) {
            CP_WAIT2();
            __syncthreads();
            COMPUTE(it);
            if (it < 13) issue_AB(H1p + (it + 3) * 64, PB1 + (it + 3) * 4096,
                                  AsBase, BsBase, (it + 3) & 3, tid);
            else         issue_B(PB2 + (it - 13) * 4096, BsBase, (it - 13) & 3, tid);
            CP_COMMIT();
        }

        // ---- layer-0 elementwise -> h1[q], c1 ----
        #pragma unroll
        for (int rh = 0; rh < 2; rh++) {
            __half hh[2];
            #pragma unroll
            for (int c = 0; c < 2; c++) {
                int r = rh * 2 + c;
                float si = acc[0][r] + gx[0][r];
                float sf = acc[1][r] + gx[1][r];
                float sg = acc[2][r] + gx[2][r];
                float so = acc[3][r] + gx[3][r];
                float cv = sigf(sf) * c1r[r] + sigf(si) * tanh_fast(sg);
                c1r[r] = cv;
                hh[c] = __float2half_rn(sigf(so) * tanh_fast(cv));
            }
            int row = rowb + rh * 8;
            __half2 hv; hv.x = hh[0]; hv.y = hh[1];
            __stcg(reinterpret_cast<__half2*>(&g_h1[q][row * 1024 + hoff]), hv);
        }

        grid_barrier();   // the single per-timestep grid sync

        // complete L1 chunks 0..2 with their A halves (h1[q], valid post-barrier)
        issue_A(H1q,       AsBase, 0, tid); CP_COMMIT();
        issue_A(H1q + 64,  AsBase, 1, tid); CP_COMMIT();
        issue_A(H1q + 128, AsBase, 2, tid); CP_COMMIT();

        // ---- layer 1 GEMM; tail issues L0(t+1) chunks 0..2 (A = h1[q], valid) ----
        ZACC();
        #pragma unroll 4
        for (int it = 0; it < 32; it++) {
            CP_WAIT2();
            __syncthreads();
            COMPUTE(it);
            if (it < 29) {
                int c = it + 3;
                const __half* A_ = (c < 16) ? (H1q + c * 64) : (H2p + (c - 16) * 64);
                const __half* B_ = ((c < 16) ? PB2 : PB3) + (c & 15) * 4096;
                issue_AB(A_, B_, AsBase, BsBase, c & 3, tid);
            } else if (t < TT - 1) {
                int c = it - 29;
                issue_AB(H1q + c * 64, PB1 + c * 4096, AsBase, BsBase, c & 3, tid);
            }
            CP_COMMIT();
        }

        // ---- layer-1 elementwise -> h2[q], c2, out ----
        #pragma unroll
        for (int rh = 0; rh < 2; rh++) {
            float ho[2];
            __half hh[2];
            #pragma unroll
            for (int c = 0; c < 2; c++) {
                int r = rh * 2 + c;
                float si = acc[0][r] + b1r[0][c];
                float sf = acc[1][r] + b1r[1][c];
                float sg = acc[2][r] + b1r[2][c];
                float so = acc[3][r] + b1r[3][c];
                float cv = sigf(sf) * c2r[r] + sigf(si) * tanh_fast(sg);
                c2r[r] = cv;
                float h = sigf(so) * tanh_fast(cv);
                ho[c] = h;
                hh[c] = __float2half_rn(h);
            }
            int row = rowb + rh * 8;
            __half2 hv; hv.x = hh[0]; hv.y = hh[1];
            __stcg(reinterpret_cast<__half2*>(&g_h2[q][row * 1024 + hoff]), hv);
            *reinterpret_cast<float2*>(out + ((size_t)row * TT + t) * 1024 + jlog) =
                make_float2(ho[0], ho[1]);   // full-precision output
        }
    }
    #undef ZACC
    #undef COMPUTE
}

// ---------------- launch ----------------
extern "C" void kernel_launch(void* const* d_in, const int* in_sizes, int n_in,
                              void* d_out, int out_size) {
    const float* x    = (const float*)d_in[0];
    const float* fc_w = (const float*)d_in[1];
    const float* fc_b = (const float*)d_in[2];
    const float* Wih0 = (const float*)d_in[3];
    const float* Whh0 = (const float*)d_in[4];
    const float* bih0 = (const float*)d_in[5];
    const float* bhh0 = (const float*)d_in[6];
    const float* Wih1 = (const float*)d_in[7];
    const float* Whh1 = (const float*)d_in[8];
    const float* bih1 = (const float*)d_in[9];
    const float* bhh1 = (const float*)d_in[10];
    float* out = (float*)d_out;

    static int smem_set = 0;
    const int smem_bytes = 2 * NSTAGE * TILEW * 4;   // 81920
    if (!smem_set) {
        cudaFuncSetAttribute(lstm_persistent,
                             cudaFuncAttributeMaxDynamicSharedMemorySize, smem_bytes);
        smem_set = 1;
    }

    init_zero_kernel<<<1024, 256>>>();
    pack_kernel<<<65536, 256>>>(Wih0, Whh0, Wih1, Whh1);
    fc_kernel<<<512, 256>>>(x, fc_w, fc_b);
    lstm_persistent<<<NBLK, NTHR, smem_bytes>>>(bih0, bhh0, bih1, bhh1, out);
}